// round 9
// baseline (speedup 1.0000x reference)
#include <cuda_runtime.h>
#include <cuda_bf16.h>
#include <cstdint>

// input  [32, 64, 56, 56] fp32 -> zero-padded halo NHWC bf16 g_inq[32][58][58][64]
// weight [128, 64, 3, 3]  fp32 -> prequantized [kk][n][c] bf16 g_Wq
// output [32, 128, 56, 56] fp32
// Implicit GEMM (mma.sync bf16). BM=128 pixels (image padded to 25 tiles).
// A = 348-halo-row window loaded once (SW128 swizzle); B triple-buffered.
// Stage compute: B fragments register-resident, A ldmatrix overlapped with MMA.

#define HW 56
#define CIN 64
#define NOUT 128
#define PIX (HW*HW)            // 3136
#define HLW 58
#define HPIX (HLW*HLW)         // 3364
#define BM 128
#define TPI 25                 // tiles per image (25*128 = 3200 >= 3136)
#define NCTA (32*TPI)          // 800
#define AROWS 348              // 6 halo rows x 58
#define A_BYTES (AROWS*128)    // 44544
#define B_BYTES (NOUT*128)     // 16384
#define SMEM_ALLOC (A_BYTES + 3*B_BYTES)   // 93696
#define PADE 132               // epilogue float stride

__device__ __align__(16) __nv_bfloat16 g_Wq[9 * NOUT * CIN];
__device__ __align__(16) __nv_bfloat16 g_inq[((size_t)32 * HPIX + 1024) * CIN]; // +slack

// Fused prep: blocks [0,288) quantize weights, rest build halo input.
__global__ void prep_all(const float* __restrict__ w, const float* __restrict__ in) {
    if (blockIdx.x < 288) {
        int idx = blockIdx.x * 256 + threadIdx.x;   // 73728
        if (idx < 9 * NOUT * CIN) {
            int c  = idx & 63;
            int n  = (idx >> 6) & 127;
            int kk = idx >> 13;
            g_Wq[idx] = __float2bfloat16(w[(n * CIN + c) * 9 + kk]);
        }
        return;
    }
    int pid = (blockIdx.x - 288) * 256 + threadIdx.x;
    if (pid >= 32 * HPIX) return;
    int b   = pid / HPIX;
    int rem = pid - b * HPIX;
    int hh  = rem / HLW;
    int ww  = rem - hh * HLW;
    __nv_bfloat16* dst = g_inq + (size_t)pid * CIN;
    bool inside = (hh >= 1) && (hh <= HW) && (ww >= 1) && (ww <= HW);
    if (inside) {
        const float* src = in + ((size_t)b * CIN) * PIX + (hh - 1) * HW + (ww - 1);
#pragma unroll
        for (int c = 0; c < CIN; c += 8) {
            __nv_bfloat16 v[8];
#pragma unroll
            for (int j = 0; j < 8; j++) v[j] = __float2bfloat16(src[(size_t)(c + j) * PIX]);
            *reinterpret_cast<uint4*>(dst + c) = *reinterpret_cast<const uint4*>(v);
        }
    } else {
        uint4 z = make_uint4(0, 0, 0, 0);
#pragma unroll
        for (int c = 0; c < CIN; c += 8) *reinterpret_cast<uint4*>(dst + c) = z;
    }
}

__device__ __forceinline__ void cp16(uint32_t dst, const void* src) {
    asm volatile("cp.async.cg.shared.global [%0], [%1], 16;\n" :: "r"(dst), "l"(src));
}
__device__ __forceinline__ void ldmatrix_x4(uint32_t* r, uint32_t addr) {
    asm volatile("ldmatrix.sync.aligned.m8n8.x4.shared.b16 {%0,%1,%2,%3}, [%4];\n"
                 : "=r"(r[0]), "=r"(r[1]), "=r"(r[2]), "=r"(r[3]) : "r"(addr));
}
__device__ __forceinline__ void mma_bf16(float* c, const uint32_t* a, const uint32_t* b) {
    asm volatile("mma.sync.aligned.m16n8k16.row.col.f32.bf16.bf16.f32 "
                 "{%0,%1,%2,%3}, {%4,%5,%6,%7}, {%8,%9}, {%0,%1,%2,%3};\n"
                 : "+f"(c[0]), "+f"(c[1]), "+f"(c[2]), "+f"(c[3])
                 : "r"(a[0]), "r"(a[1]), "r"(a[2]), "r"(a[3]),
                   "r"(b[0]), "r"(b[1]));
}
__device__ __forceinline__ void stg_cs(float* p, float v) {
    asm volatile("st.global.cs.f32 [%0], %1;" :: "l"(p), "f"(v) : "memory");
}

__global__ __launch_bounds__(256, 2)
void qconv_mma(const float* __restrict__ bias, float* __restrict__ out) {
    extern __shared__ __align__(16) unsigned char dsm[];
    __shared__ float bias_s[NOUT];
    float* Ep = reinterpret_cast<float*>(dsm);

    const int tid  = threadIdx.x;
    const int lane = tid & 31;
    const int warp = tid >> 5;
    const int wm   = (warp & 1) * 64;          // 0 or 64
    const int wn   = (warp >> 1) * 32;         // 0,32,64,96

    if (tid < NOUT) bias_s[tid] = __bfloat162float(__float2bfloat16(bias[tid]));

    // CTA geometry: image b, tile t (128 pixels, may include dummies past 3136)
    const int b  = blockIdx.x / TPI;
    const int t  = blockIdx.x - b * TPI;
    const int q0 = t * BM;
    const int oh0 = q0 / HW;
    const size_t S0 = ((size_t)b * HLW + oh0) * HLW;

    const uint32_t smem_u32 = (uint32_t)__cvta_generic_to_shared(dsm);
    const uint32_t Ab = smem_u32;

    int rb[4];
#pragma unroll
    for (int mi = 0; mi < 4; mi++) {
        int q = q0 + wm + mi * 16 + (lane & 15);
        rb[mi] = (q / HW - oh0) * HLW + (q % HW);
    }

    float acc[4][4][4];
#pragma unroll
    for (int mi = 0; mi < 4; mi++)
#pragma unroll
        for (int ni = 0; ni < 4; ni++)
#pragma unroll
            for (int j = 0; j < 4; j++) acc[mi][ni][j] = 0.f;

    // ---- prologue: A window (348 rows x 128B, SW128), one commit group ----
#pragma unroll
    for (int it = 0; it < 11; it++) {
        int idx = tid + it * 256;
        if (idx < AROWS * 8) {
            int row = idx >> 3, qc = idx & 7;
            uint32_t col = (uint32_t)(qc * 16) ^ (uint32_t)((row & 7) * 16);
            cp16(Ab + row * 128 + col, g_inq + (S0 + row) * CIN + qc * 8);
        }
    }
    asm volatile("cp.async.commit_group;\n" ::: "memory");

    // B loader
    const int brow = tid >> 1, bhalf = tid & 1;
    const uint32_t bsw = (uint32_t)((brow & 7) * 16);
    auto issueB = [&](int kk, int s) {
        const __nv_bfloat16* srcB = g_Wq + kk * (NOUT * CIN) + brow * CIN + bhalf * 32;
        uint32_t dstB = smem_u32 + A_BYTES + (uint32_t)s * B_BYTES + (uint32_t)brow * 128;
#pragma unroll
        for (int j = 0; j < 4; j++)
            cp16(dstB + (((uint32_t)(bhalf * 64 + j * 16)) ^ bsw), srcB + j * 8);
        asm volatile("cp.async.commit_group;\n" ::: "memory");
    };

    issueB(0, 0);
    issueB(1, 1);

    // B fragment lane geometry
    uint32_t brow_l[2], bswl[2];
#pragma unroll
    for (int np = 0; np < 2; np++) {
        brow_l[np] = wn + np * 16 + (lane >> 4) * 8 + (lane & 7);
        bswl[np]   = (brow_l[np] & 7) * 16;
    }
    const uint32_t bcol_half = ((lane >> 3) & 1) * 16;
    const uint32_t acol0 = (uint32_t)((lane >> 4) * 16);

#pragma unroll 1
    for (int kk = 0; kk < 9; kk++) {
        if (kk < 8) asm volatile("cp.async.wait_group 1;\n" ::: "memory");
        else        asm volatile("cp.async.wait_group 0;\n" ::: "memory");
        __syncthreads();        // stage kk data visible; stage kk-1 reads done
        if (kk < 7) issueB(kk + 2, (kk + 2) % 3);

        const int kh = kk / 3, kw = kk - kh * 3;
        const int khw = kh * HLW + kw;
        const uint32_t bbase = smem_u32 + A_BYTES + (uint32_t)(kk % 3) * B_BYTES;

        uint32_t arow128[4], asw[4];
#pragma unroll
        for (int mi = 0; mi < 4; mi++) {
            int ar = rb[mi] + khw;
            arow128[mi] = Ab + (uint32_t)ar * 128;
            asw[mi]     = (uint32_t)((ar & 7) * 16);
        }

        // ---- hoist ALL B fragments for this stage into registers ----
        uint32_t ball[4][4][2];
#pragma unroll
        for (int ks = 0; ks < 4; ks++) {
#pragma unroll
            for (int np = 0; np < 2; np++) {
                uint32_t bc = ((uint32_t)(ks * 32) | bcol_half) ^ bswl[np];
                uint32_t r4[4];
                ldmatrix_x4(r4, bbase + brow_l[np] * 128 + bc);
                ball[ks][np * 2][0]     = r4[0]; ball[ks][np * 2][1]     = r4[1];
                ball[ks][np * 2 + 1][0] = r4[2]; ball[ks][np * 2 + 1][1] = r4[3];
            }
        }

        // ---- ks loop: only A ldmatrix on the critical path ----
#pragma unroll
        for (int ks = 0; ks < 4; ks++) {
            const uint32_t ac = (uint32_t)(ks * 32) | acol0;
            uint32_t af[4][4];
#pragma unroll
            for (int mi = 0; mi < 4; mi++)
                ldmatrix_x4(af[mi], arow128[mi] + (ac ^ asw[mi]));
#pragma unroll
            for (int mi = 0; mi < 4; mi++)
#pragma unroll
                for (int ni = 0; ni < 4; ni++)
                    mma_bf16(acc[mi][ni], af[mi], ball[ks][ni]);
        }
    }
    __syncthreads();            // all stage-8 reads done before Ep overwrite

    // ---- epilogue: smem transpose, two 64-channel passes ----
    const int m_l  = tid & 127;
    const int half = tid >> 7;
    const int qme  = q0 + m_l;
    float* ob = out + (size_t)b * (NOUT * PIX);

#pragma unroll 1
    for (int p = 0; p < 2; p++) {
        if ((wn >> 6) == p) {
#pragma unroll
            for (int mi = 0; mi < 4; mi++)
#pragma unroll
                for (int ni = 0; ni < 4; ni++) {
                    int ncol = (wn & 63) + ni * 8 + 2 * (lane & 3);
                    int mrow = wm + mi * 16 + (lane >> 2);
                    Ep[(ncol + 0) * PADE + mrow]     = acc[mi][ni][0];
                    Ep[(ncol + 1) * PADE + mrow]     = acc[mi][ni][1];
                    Ep[(ncol + 0) * PADE + mrow + 8] = acc[mi][ni][2];
                    Ep[(ncol + 1) * PADE + mrow + 8] = acc[mi][ni][3];
                }
        }
        __syncthreads();
        if (qme < PIX) {
#pragma unroll
            for (int i = 0; i < 32; i++) {
                int n_l = half + 2 * i;
                float v = Ep[n_l * PADE + m_l] + bias_s[p * 64 + n_l];
                stg_cs(ob + (size_t)(p * 64 + n_l) * PIX + qme, v);
            }
        }
        __syncthreads();
    }
}

extern "C" void kernel_launch(void* const* d_in, const int* in_sizes, int n_in,
                              void* d_out, int out_size) {
    const float* inp    = (const float*)d_in[0];
    const float* weight = (const float*)d_in[1];
    const float* bias   = (const float*)d_in[2];
    float* out = (float*)d_out;
    (void)in_sizes; (void)n_in; (void)out_size;

    cudaFuncSetAttribute(qconv_mma, cudaFuncAttributeMaxDynamicSharedMemorySize, SMEM_ALLOC);

    prep_all<<<288 + (32 * HPIX + 255) / 256, 256>>>(weight, inp);
    qconv_mma<<<NCTA, 256, SMEM_ALLOC>>>(bias, out);
}

// round 11
// speedup vs baseline: 1.0085x; 1.0085x over previous
#include <cuda_runtime.h>
#include <cuda_bf16.h>
#include <cstdint>

// input  [32, 64, 56, 56] fp32 -> zero-padded halo NHWC bf16 g_inq[32][58][58][64]
// weight [128, 64, 3, 3]  fp32 -> prequantized [kk][n][c] bf16 g_Wq
// output [32, 128, 56, 56] fp32
// Implicit GEMM (mma.sync bf16). BM=128 pixels (image padded to 25 tiles).
// A = 348-halo-row window loaded once (SW128 swizzle); B triple-buffered.
// Prep uses cvt.rn.bf16x2.f32 (2 quantizations / instruction).

#define HW 56
#define CIN 64
#define NOUT 128
#define PIX (HW*HW)            // 3136
#define HLW 58
#define HPIX (HLW*HLW)         // 3364
#define BM 128
#define TPI 25                 // tiles per image (25*128 = 3200 >= 3136)
#define NCTA (32*TPI)          // 800
#define AROWS 348              // 6 halo rows x 58
#define A_BYTES (AROWS*128)    // 44544
#define B_BYTES (NOUT*128)     // 16384
#define SMEM_ALLOC (A_BYTES + 3*B_BYTES)   // 93696
#define PADE 132               // epilogue float stride

__device__ __align__(16) __nv_bfloat16 g_Wq[9 * NOUT * CIN];
__device__ __align__(16) __nv_bfloat16 g_inq[((size_t)32 * HPIX + 1024) * CIN]; // +slack

__device__ __forceinline__ uint32_t cvt2(float hi, float lo) {
    uint32_t r;
    asm("cvt.rn.bf16x2.f32 %0, %1, %2;" : "=r"(r) : "f"(hi), "f"(lo));
    return r;
}
__device__ __forceinline__ float ldcs(const float* p) {
    float v;
    asm("ld.global.cs.f32 %0, [%1];" : "=f"(v) : "l"(p));
    return v;
}

// Fused prep: blocks [0,288) quantize weights, rest build halo input.
__global__ void prep_all(const float* __restrict__ w, const float* __restrict__ in) {
    if (blockIdx.x < 288) {
        int idx = blockIdx.x * 256 + threadIdx.x;   // 73728
        if (idx < 9 * NOUT * CIN) {
            int c  = idx & 63;
            int n  = (idx >> 6) & 127;
            int kk = idx >> 13;
            g_Wq[idx] = __float2bfloat16(w[(n * CIN + c) * 9 + kk]);
        }
        return;
    }
    int pid = (blockIdx.x - 288) * 256 + threadIdx.x;
    if (pid >= 32 * HPIX) return;
    int b   = pid / HPIX;
    int rem = pid - b * HPIX;
    int hh  = rem / HLW;
    int ww  = rem - hh * HLW;
    __nv_bfloat16* dst = g_inq + (size_t)pid * CIN;
    bool inside = (hh >= 1) && (hh <= HW) && (ww >= 1) && (ww <= HW);
    if (inside) {
        const float* src = in + ((size_t)b * CIN) * PIX + (hh - 1) * HW + (ww - 1);
#pragma unroll
        for (int c = 0; c < CIN; c += 8) {
            float f[8];
#pragma unroll
            for (int j = 0; j < 8; j++) f[j] = ldcs(src + (size_t)(c + j) * PIX);
            uint4 v;
            v.x = cvt2(f[1], f[0]);
            v.y = cvt2(f[3], f[2]);
            v.z = cvt2(f[5], f[4]);
            v.w = cvt2(f[7], f[6]);
            *reinterpret_cast<uint4*>(dst + c) = v;
        }
    } else {
        uint4 z = make_uint4(0, 0, 0, 0);
#pragma unroll
        for (int c = 0; c < CIN; c += 8) *reinterpret_cast<uint4*>(dst + c) = z;
    }
}

__device__ __forceinline__ void cp16(uint32_t dst, const void* src) {
    asm volatile("cp.async.cg.shared.global [%0], [%1], 16;\n" :: "r"(dst), "l"(src));
}
__device__ __forceinline__ void ldmatrix_x4(uint32_t* r, uint32_t addr) {
    asm volatile("ldmatrix.sync.aligned.m8n8.x4.shared.b16 {%0,%1,%2,%3}, [%4];\n"
                 : "=r"(r[0]), "=r"(r[1]), "=r"(r[2]), "=r"(r[3]) : "r"(addr));
}
__device__ __forceinline__ void mma_bf16(float* c, const uint32_t* a, const uint32_t* b) {
    asm volatile("mma.sync.aligned.m16n8k16.row.col.f32.bf16.bf16.f32 "
                 "{%0,%1,%2,%3}, {%4,%5,%6,%7}, {%8,%9}, {%0,%1,%2,%3};\n"
                 : "+f"(c[0]), "+f"(c[1]), "+f"(c[2]), "+f"(c[3])
                 : "r"(a[0]), "r"(a[1]), "r"(a[2]), "r"(a[3]),
                   "r"(b[0]), "r"(b[1]));
}
__device__ __forceinline__ void stg_cs(float* p, float v) {
    asm volatile("st.global.cs.f32 [%0], %1;" :: "l"(p), "f"(v) : "memory");
}

__global__ __launch_bounds__(256, 2)
void qconv_mma(const float* __restrict__ bias, float* __restrict__ out) {
    extern __shared__ __align__(16) unsigned char dsm[];
    __shared__ float bias_s[NOUT];
    float* Ep = reinterpret_cast<float*>(dsm);

    const int tid  = threadIdx.x;
    const int lane = tid & 31;
    const int warp = tid >> 5;
    const int wm   = (warp & 1) * 64;          // 0 or 64
    const int wn   = (warp >> 1) * 32;         // 0,32,64,96

    if (tid < NOUT) bias_s[tid] = __bfloat162float(__float2bfloat16(bias[tid]));

    // CTA geometry: image b, tile t (128 pixels, may include dummies past 3136)
    const int b  = blockIdx.x / TPI;
    const int t  = blockIdx.x - b * TPI;
    const int q0 = t * BM;
    const int oh0 = q0 / HW;
    const size_t S0 = ((size_t)b * HLW + oh0) * HLW;

    const uint32_t smem_u32 = (uint32_t)__cvta_generic_to_shared(dsm);
    const uint32_t Ab = smem_u32;

    int rb[4];
#pragma unroll
    for (int mi = 0; mi < 4; mi++) {
        int q = q0 + wm + mi * 16 + (lane & 15);
        rb[mi] = (q / HW - oh0) * HLW + (q % HW);
    }

    float acc[4][4][4];
#pragma unroll
    for (int mi = 0; mi < 4; mi++)
#pragma unroll
        for (int ni = 0; ni < 4; ni++)
#pragma unroll
            for (int j = 0; j < 4; j++) acc[mi][ni][j] = 0.f;

    // ---- prologue: A window (348 rows x 128B, SW128), one commit group ----
#pragma unroll
    for (int it = 0; it < 11; it++) {
        int idx = tid + it * 256;
        if (idx < AROWS * 8) {
            int row = idx >> 3, qc = idx & 7;
            uint32_t col = (uint32_t)(qc * 16) ^ (uint32_t)((row & 7) * 16);
            cp16(Ab + row * 128 + col, g_inq + (S0 + row) * CIN + qc * 8);
        }
    }
    asm volatile("cp.async.commit_group;\n" ::: "memory");

    // B loader
    const int brow = tid >> 1, bhalf = tid & 1;
    const uint32_t bsw = (uint32_t)((brow & 7) * 16);
    auto issueB = [&](int kk, int s) {
        const __nv_bfloat16* srcB = g_Wq + kk * (NOUT * CIN) + brow * CIN + bhalf * 32;
        uint32_t dstB = smem_u32 + A_BYTES + (uint32_t)s * B_BYTES + (uint32_t)brow * 128;
#pragma unroll
        for (int j = 0; j < 4; j++)
            cp16(dstB + (((uint32_t)(bhalf * 64 + j * 16)) ^ bsw), srcB + j * 8);
        asm volatile("cp.async.commit_group;\n" ::: "memory");
    };

    issueB(0, 0);
    issueB(1, 1);

    // B fragment lane geometry
    uint32_t brow_l[2], bswl[2];
#pragma unroll
    for (int np = 0; np < 2; np++) {
        brow_l[np] = wn + np * 16 + (lane >> 4) * 8 + (lane & 7);
        bswl[np]   = (brow_l[np] & 7) * 16;
    }
    const uint32_t bcol_half = ((lane >> 3) & 1) * 16;
    const uint32_t acol0 = (uint32_t)((lane >> 4) * 16);

#pragma unroll 1
    for (int kk = 0; kk < 9; kk++) {
        if (kk < 8) asm volatile("cp.async.wait_group 1;\n" ::: "memory");
        else        asm volatile("cp.async.wait_group 0;\n" ::: "memory");
        __syncthreads();        // stage kk data visible; stage kk-1 reads done
        if (kk < 7) issueB(kk + 2, (kk + 2) % 3);

        const int kh = kk / 3, kw = kk - kh * 3;
        const int khw = kh * HLW + kw;
        const uint32_t bbase = smem_u32 + A_BYTES + (uint32_t)(kk % 3) * B_BYTES;

        uint32_t arow128[4], asw[4];
#pragma unroll
        for (int mi = 0; mi < 4; mi++) {
            int ar = rb[mi] + khw;
            arow128[mi] = Ab + (uint32_t)ar * 128;
            asw[mi]     = (uint32_t)((ar & 7) * 16);
        }

#pragma unroll
        for (int ks = 0; ks < 4; ks++) {
            const uint32_t ac = (uint32_t)(ks * 32) | acol0;
            uint32_t af[4][4];
#pragma unroll
            for (int mi = 0; mi < 4; mi++)
                ldmatrix_x4(af[mi], arow128[mi] + (ac ^ asw[mi]));

            uint32_t bfr[4][2];
#pragma unroll
            for (int np = 0; np < 2; np++) {
                uint32_t bc = ((uint32_t)(ks * 32) | bcol_half) ^ bswl[np];
                uint32_t r4[4];
                ldmatrix_x4(r4, bbase + brow_l[np] * 128 + bc);
                bfr[np * 2][0] = r4[0]; bfr[np * 2][1] = r4[1];
                bfr[np * 2 + 1][0] = r4[2]; bfr[np * 2 + 1][1] = r4[3];
            }
#pragma unroll
            for (int mi = 0; mi < 4; mi++)
#pragma unroll
                for (int ni = 0; ni < 4; ni++)
                    mma_bf16(acc[mi][ni], af[mi], bfr[ni]);
        }
    }
    __syncthreads();            // all stage-8 reads done before Ep overwrite

    // ---- epilogue: smem transpose, two 64-channel passes ----
    const int m_l  = tid & 127;
    const int half = tid >> 7;
    const int qme  = q0 + m_l;
    float* ob = out + (size_t)b * (NOUT * PIX);

#pragma unroll 1
    for (int p = 0; p < 2; p++) {
        if ((wn >> 6) == p) {
#pragma unroll
            for (int mi = 0; mi < 4; mi++)
#pragma unroll
                for (int ni = 0; ni < 4; ni++) {
                    int ncol = (wn & 63) + ni * 8 + 2 * (lane & 3);
                    int mrow = wm + mi * 16 + (lane >> 2);
                    Ep[(ncol + 0) * PADE + mrow]     = acc[mi][ni][0];
                    Ep[(ncol + 1) * PADE + mrow]     = acc[mi][ni][1];
                    Ep[(ncol + 0) * PADE + mrow + 8] = acc[mi][ni][2];
                    Ep[(ncol + 1) * PADE + mrow + 8] = acc[mi][ni][3];
                }
        }
        __syncthreads();
        if (qme < PIX) {
#pragma unroll
            for (int i = 0; i < 32; i++) {
                int n_l = half + 2 * i;
                float v = Ep[n_l * PADE + m_l] + bias_s[p * 64 + n_l];
                stg_cs(ob + (size_t)(p * 64 + n_l) * PIX + qme, v);
            }
        }
        __syncthreads();
    }
}

extern "C" void kernel_launch(void* const* d_in, const int* in_sizes, int n_in,
                              void* d_out, int out_size) {
    const float* inp    = (const float*)d_in[0];
    const float* weight = (const float*)d_in[1];
    const float* bias   = (const float*)d_in[2];
    float* out = (float*)d_out;
    (void)in_sizes; (void)n_in; (void)out_size;

    cudaFuncSetAttribute(qconv_mma, cudaFuncAttributeMaxDynamicSharedMemorySize, SMEM_ALLOC);

    prep_all<<<288 + (32 * HPIX + 255) / 256, 256>>>(weight, inp);
    qconv_mma<<<NCTA, 256, SMEM_ALLOC>>>(bias, out);
}

// round 12
// speedup vs baseline: 1.0603x; 1.0513x over previous
#include <cuda_runtime.h>
#include <cuda_bf16.h>
#include <cstdint>

// input  [32, 64, 56, 56] fp32 -> zero-padded halo NHWC bf16 g_inq[32][58][58][64]
// weight [128, 64, 3, 3]  fp32 -> prequantized [kk][n][c] bf16 g_Wq
// output [32, 128, 56, 56] fp32
// Implicit GEMM (mma.sync bf16). BM=128 pixels (image padded to 25 tiles).
// A = 348-halo-row window loaded once (SW128 swizzle); B triple-buffered.
// Prep: 4 threads/pixel (16 ch each) -> fully coalesced 1KB/warp stores.

#define HW 56
#define CIN 64
#define NOUT 128
#define PIX (HW*HW)            // 3136
#define HLW 58
#define HPIX (HLW*HLW)         // 3364
#define BM 128
#define TPI 25                 // tiles per image (25*128 = 3200 >= 3136)
#define NCTA (32*TPI)          // 800
#define AROWS 348              // 6 halo rows x 58
#define A_BYTES (AROWS*128)    // 44544
#define B_BYTES (NOUT*128)     // 16384
#define SMEM_ALLOC (A_BYTES + 3*B_BYTES)   // 93696
#define PADE 132               // epilogue float stride
#define PREP_IN_BLOCKS ((32*HPIX*4 + 255)/256)   // 1682

__device__ __align__(16) __nv_bfloat16 g_Wq[9 * NOUT * CIN];
__device__ __align__(16) __nv_bfloat16 g_inq[((size_t)32 * HPIX + 1024) * CIN]; // +slack

__device__ __forceinline__ uint32_t cvt2(float hi, float lo) {
    uint32_t r;
    asm("cvt.rn.bf16x2.f32 %0, %1, %2;" : "=r"(r) : "f"(hi), "f"(lo));
    return r;
}
__device__ __forceinline__ float ldcs(const float* p) {
    float v;
    asm("ld.global.cs.f32 %0, [%1];" : "=f"(v) : "l"(p));
    return v;
}

// Fused prep: blocks [0,288) quantize weights, rest build halo input
// (4 threads per halo pixel, 16 channels each).
__global__ void prep_all(const float* __restrict__ w, const float* __restrict__ in) {
    if (blockIdx.x < 288) {
        int idx = blockIdx.x * 256 + threadIdx.x;   // 73728
        if (idx < 9 * NOUT * CIN) {
            int c  = idx & 63;
            int n  = (idx >> 6) & 127;
            int kk = idx >> 13;
            g_Wq[idx] = __float2bfloat16(w[(n * CIN + c) * 9 + kk]);
        }
        return;
    }
    int gid = (blockIdx.x - 288) * 256 + threadIdx.x;
    int pid = gid >> 2;                 // halo pixel
    int cg  = (gid & 3) * 16;           // channel group base
    if (pid >= 32 * HPIX) return;
    int b   = pid / HPIX;
    int rem = pid - b * HPIX;
    int hh  = rem / HLW;
    int ww  = rem - hh * HLW;
    __nv_bfloat16* dst = g_inq + (size_t)pid * CIN + cg;
    bool inside = (hh >= 1) && (hh <= HW) && (ww >= 1) && (ww <= HW);
    if (inside) {
        const float* src = in + ((size_t)b * CIN + cg) * PIX + (hh - 1) * HW + (ww - 1);
        float f[16];
#pragma unroll
        for (int j = 0; j < 16; j++) f[j] = ldcs(src + (size_t)j * PIX);
        uint4 v0, v1;
        v0.x = cvt2(f[1],  f[0]);  v0.y = cvt2(f[3],  f[2]);
        v0.z = cvt2(f[5],  f[4]);  v0.w = cvt2(f[7],  f[6]);
        v1.x = cvt2(f[9],  f[8]);  v1.y = cvt2(f[11], f[10]);
        v1.z = cvt2(f[13], f[12]); v1.w = cvt2(f[15], f[14]);
        *reinterpret_cast<uint4*>(dst)     = v0;
        *reinterpret_cast<uint4*>(dst + 8) = v1;
    } else {
        uint4 z = make_uint4(0, 0, 0, 0);
        *reinterpret_cast<uint4*>(dst)     = z;
        *reinterpret_cast<uint4*>(dst + 8) = z;
    }
}

__device__ __forceinline__ void cp16(uint32_t dst, const void* src) {
    asm volatile("cp.async.cg.shared.global [%0], [%1], 16;\n" :: "r"(dst), "l"(src));
}
__device__ __forceinline__ void ldmatrix_x4(uint32_t* r, uint32_t addr) {
    asm volatile("ldmatrix.sync.aligned.m8n8.x4.shared.b16 {%0,%1,%2,%3}, [%4];\n"
                 : "=r"(r[0]), "=r"(r[1]), "=r"(r[2]), "=r"(r[3]) : "r"(addr));
}
__device__ __forceinline__ void mma_bf16(float* c, const uint32_t* a, const uint32_t* b) {
    asm volatile("mma.sync.aligned.m16n8k16.row.col.f32.bf16.bf16.f32 "
                 "{%0,%1,%2,%3}, {%4,%5,%6,%7}, {%8,%9}, {%0,%1,%2,%3};\n"
                 : "+f"(c[0]), "+f"(c[1]), "+f"(c[2]), "+f"(c[3])
                 : "r"(a[0]), "r"(a[1]), "r"(a[2]), "r"(a[3]),
                   "r"(b[0]), "r"(b[1]));
}
__device__ __forceinline__ void stg_cs(float* p, float v) {
    asm volatile("st.global.cs.f32 [%0], %1;" :: "l"(p), "f"(v) : "memory");
}

__global__ __launch_bounds__(256, 2)
void qconv_mma(const float* __restrict__ bias, float* __restrict__ out) {
    extern __shared__ __align__(16) unsigned char dsm[];
    __shared__ float bias_s[NOUT];
    float* Ep = reinterpret_cast<float*>(dsm);

    const int tid  = threadIdx.x;
    const int lane = tid & 31;
    const int warp = tid >> 5;
    const int wm   = (warp & 1) * 64;          // 0 or 64
    const int wn   = (warp >> 1) * 32;         // 0,32,64,96

    if (tid < NOUT) bias_s[tid] = __bfloat162float(__float2bfloat16(bias[tid]));

    // CTA geometry: image b, tile t (128 pixels, may include dummies past 3136)
    const int b  = blockIdx.x / TPI;
    const int t  = blockIdx.x - b * TPI;
    const int q0 = t * BM;
    const int oh0 = q0 / HW;
    const size_t S0 = ((size_t)b * HLW + oh0) * HLW;

    const uint32_t smem_u32 = (uint32_t)__cvta_generic_to_shared(dsm);
    const uint32_t Ab = smem_u32;

    int rb[4];
#pragma unroll
    for (int mi = 0; mi < 4; mi++) {
        int q = q0 + wm + mi * 16 + (lane & 15);
        rb[mi] = (q / HW - oh0) * HLW + (q % HW);
    }

    float acc[4][4][4];
#pragma unroll
    for (int mi = 0; mi < 4; mi++)
#pragma unroll
        for (int ni = 0; ni < 4; ni++)
#pragma unroll
            for (int j = 0; j < 4; j++) acc[mi][ni][j] = 0.f;

    // ---- prologue: A window (348 rows x 128B, SW128), one commit group ----
#pragma unroll
    for (int it = 0; it < 11; it++) {
        int idx = tid + it * 256;
        if (idx < AROWS * 8) {
            int row = idx >> 3, qc = idx & 7;
            uint32_t col = (uint32_t)(qc * 16) ^ (uint32_t)((row & 7) * 16);
            cp16(Ab + row * 128 + col, g_inq + (S0 + row) * CIN + qc * 8);
        }
    }
    asm volatile("cp.async.commit_group;\n" ::: "memory");

    // B loader
    const int brow = tid >> 1, bhalf = tid & 1;
    const uint32_t bsw = (uint32_t)((brow & 7) * 16);
    auto issueB = [&](int kk, int s) {
        const __nv_bfloat16* srcB = g_Wq + kk * (NOUT * CIN) + brow * CIN + bhalf * 32;
        uint32_t dstB = smem_u32 + A_BYTES + (uint32_t)s * B_BYTES + (uint32_t)brow * 128;
#pragma unroll
        for (int j = 0; j < 4; j++)
            cp16(dstB + (((uint32_t)(bhalf * 64 + j * 16)) ^ bsw), srcB + j * 8);
        asm volatile("cp.async.commit_group;\n" ::: "memory");
    };

    issueB(0, 0);
    issueB(1, 1);

    // B fragment lane geometry
    uint32_t brow_l[2], bswl[2];
#pragma unroll
    for (int np = 0; np < 2; np++) {
        brow_l[np] = wn + np * 16 + (lane >> 4) * 8 + (lane & 7);
        bswl[np]   = (brow_l[np] & 7) * 16;
    }
    const uint32_t bcol_half = ((lane >> 3) & 1) * 16;
    const uint32_t acol0 = (uint32_t)((lane >> 4) * 16);

#pragma unroll 1
    for (int kk = 0; kk < 9; kk++) {
        if (kk < 8) asm volatile("cp.async.wait_group 1;\n" ::: "memory");
        else        asm volatile("cp.async.wait_group 0;\n" ::: "memory");
        __syncthreads();        // stage kk data visible; stage kk-1 reads done
        if (kk < 7) issueB(kk + 2, (kk + 2) % 3);

        const int kh = kk / 3, kw = kk - kh * 3;
        const int khw = kh * HLW + kw;
        const uint32_t bbase = smem_u32 + A_BYTES + (uint32_t)(kk % 3) * B_BYTES;

        uint32_t arow128[4], asw[4];
#pragma unroll
        for (int mi = 0; mi < 4; mi++) {
            int ar = rb[mi] + khw;
            arow128[mi] = Ab + (uint32_t)ar * 128;
            asw[mi]     = (uint32_t)((ar & 7) * 16);
        }

#pragma unroll
        for (int ks = 0; ks < 4; ks++) {
            const uint32_t ac = (uint32_t)(ks * 32) | acol0;
            uint32_t af[4][4];
#pragma unroll
            for (int mi = 0; mi < 4; mi++)
                ldmatrix_x4(af[mi], arow128[mi] + (ac ^ asw[mi]));

            uint32_t bfr[4][2];
#pragma unroll
            for (int np = 0; np < 2; np++) {
                uint32_t bc = ((uint32_t)(ks * 32) | bcol_half) ^ bswl[np];
                uint32_t r4[4];
                ldmatrix_x4(r4, bbase + brow_l[np] * 128 + bc);
                bfr[np * 2][0] = r4[0]; bfr[np * 2][1] = r4[1];
                bfr[np * 2 + 1][0] = r4[2]; bfr[np * 2 + 1][1] = r4[3];
            }
#pragma unroll
            for (int mi = 0; mi < 4; mi++)
#pragma unroll
                for (int ni = 0; ni < 4; ni++)
                    mma_bf16(acc[mi][ni], af[mi], bfr[ni]);
        }
    }
    __syncthreads();            // all stage-8 reads done before Ep overwrite

    // ---- epilogue: smem transpose, two 64-channel passes ----
    const int m_l  = tid & 127;
    const int half = tid >> 7;
    const int qme  = q0 + m_l;
    float* ob = out + (size_t)b * (NOUT * PIX);

#pragma unroll 1
    for (int p = 0; p < 2; p++) {
        if ((wn >> 6) == p) {
#pragma unroll
            for (int mi = 0; mi < 4; mi++)
#pragma unroll
                for (int ni = 0; ni < 4; ni++) {
                    int ncol = (wn & 63) + ni * 8 + 2 * (lane & 3);
                    int mrow = wm + mi * 16 + (lane >> 2);
                    Ep[(ncol + 0) * PADE + mrow]     = acc[mi][ni][0];
                    Ep[(ncol + 1) * PADE + mrow]     = acc[mi][ni][1];
                    Ep[(ncol + 0) * PADE + mrow + 8] = acc[mi][ni][2];
                    Ep[(ncol + 1) * PADE + mrow + 8] = acc[mi][ni][3];
                }
        }
        __syncthreads();
        if (qme < PIX) {
#pragma unroll
            for (int i = 0; i < 32; i++) {
                int n_l = half + 2 * i;
                float v = Ep[n_l * PADE + m_l] + bias_s[p * 64 + n_l];
                stg_cs(ob + (size_t)(p * 64 + n_l) * PIX + qme, v);
            }
        }
        __syncthreads();
    }
}

extern "C" void kernel_launch(void* const* d_in, const int* in_sizes, int n_in,
                              void* d_out, int out_size) {
    const float* inp    = (const float*)d_in[0];
    const float* weight = (const float*)d_in[1];
    const float* bias   = (const float*)d_in[2];
    float* out = (float*)d_out;
    (void)in_sizes; (void)n_in; (void)out_size;

    cudaFuncSetAttribute(qconv_mma, cudaFuncAttributeMaxDynamicSharedMemorySize, SMEM_ALLOC);

    prep_all<<<288 + PREP_IN_BLOCKS, 256>>>(weight, inp);
    qconv_mma<<<NCTA, 256, SMEM_ALLOC>>>(bias, out);
}